// round 3
// baseline (speedup 1.0000x reference)
#include <cuda_runtime.h>
#include <math.h>

#define FDIM 512
#define F4   128           // float4 per feature row
#define NMAX 20608
#define EMAX 335872
#define TDK  0.1f
#define DT   0.2f          // DIFF_T / NUM_STEPS
#define LNEPS 1e-5f

// ---------------- device scratch (no allocations allowed) ----------------
__device__ float g_h0[(size_t)NMAX * FDIM];
__device__ float g_h1[(size_t)NMAX * FDIM];
__device__ float g_dinv[NMAX];     // deg accumulate -> dinv
__device__ float g_ewself[NMAX];
__device__ int   g_cnt[NMAX];
__device__ int   g_cur[NMAX];
__device__ int   g_rp[NMAX + 1];
__device__ int2  g_edge[EMAX];     // (src, bits(ew))
__device__ int   g_tmaxbits;

// graph_time may arrive as int32 or float32 scalar; disambiguate by bits.
__device__ __forceinline__ float decode_scalar(const void* p) {
    int iv = *(const int*)p;
    float fv = __int_as_float(iv);
    float fa = fabsf(fv);
    if (isfinite(fv) && fa >= 1e-3f && fa <= 1e9f) return fv;
    return (float)iv;
}

// ---------------- prep kernels ----------------
__global__ void k_init(int n) {
    int i = blockIdx.x * blockDim.x + threadIdx.x;
    if (i < n) { g_dinv[i] = 0.f; g_cnt[i] = 0; g_cur[i] = 0; }
    if (i == 0) g_tmaxbits = 0;
}

__global__ void k_max(const float* __restrict__ ts, int e, const void* gt) {
    int i = blockIdx.x * blockDim.x + threadIdx.x;
    float m = -1.f;
    for (int k = i; k < e; k += gridDim.x * blockDim.x) m = fmaxf(m, ts[k]);
    if (i == 0) m = fmaxf(m, decode_scalar(gt));
    #pragma unroll
    for (int off = 16; off; off >>= 1)
        m = fmaxf(m, __shfl_xor_sync(0xffffffffu, m, off));
    if ((threadIdx.x & 31) == 0)
        atomicMax(&g_tmaxbits, __float_as_int(m));
}

__global__ void k_edge_deg(const int* __restrict__ ei, const float* __restrict__ ts, int e) {
    int i = blockIdx.x * blockDim.x + threadIdx.x;
    if (i >= e) return;
    float tmax = __int_as_float(g_tmaxbits);
    int dst = ei[e + i];
    float w = expf(-TDK * (tmax - ts[i]));
    atomicAdd(&g_dinv[dst], w);
    atomicAdd(&g_cnt[dst], 1);
}

__global__ void k_node(int n, const void* gt) {
    int v = blockIdx.x * blockDim.x + threadIdx.x;
    if (v >= n) return;
    float tmax = __int_as_float(g_tmaxbits);
    float ws = expf(-TDK * (tmax - decode_scalar(gt)));
    float d = g_dinv[v] + ws;
    float di = (d > 0.f) ? rsqrtf(d) : 0.f;
    g_dinv[v] = di;
    g_ewself[v] = di * di * ws;
}

__global__ void k_scan(int n) {
    __shared__ int s[1024];
    __shared__ int s_carry;
    int tid = threadIdx.x;
    if (tid == 0) s_carry = 0;
    __syncthreads();
    for (int base = 0; base < n; base += 1024) {
        int i = base + tid;
        int v = (i < n) ? g_cnt[i] : 0;
        s[tid] = v;
        __syncthreads();
        #pragma unroll
        for (int off = 1; off < 1024; off <<= 1) {
            int t = (tid >= off) ? s[tid - off] : 0;
            __syncthreads();
            s[tid] += t;
            __syncthreads();
        }
        int carry = s_carry;
        int tot = s[1023];
        __syncthreads();
        if (i < n) g_rp[i] = carry + s[tid] - v;   // exclusive
        if (tid == 0) s_carry = carry + tot;
        __syncthreads();
    }
    if (tid == 0) g_rp[n] = s_carry;
}

__global__ void k_scatter(const int* __restrict__ ei, const float* __restrict__ ts, int e) {
    int i = blockIdx.x * blockDim.x + threadIdx.x;
    if (i >= e) return;
    float tmax = __int_as_float(g_tmaxbits);
    int src = ei[i];
    int dst = ei[e + i];
    float w = expf(-TDK * (tmax - ts[i]));
    int pos = g_rp[dst] + atomicAdd(&g_cur[dst], 1);
    g_edge[pos] = make_int2(src, __float_as_int(g_dinv[src] * w * g_dinv[dst]));
}

// ---------------- diffusion step: one block per dst node ----------------
__global__ void k_diff(const float4* __restrict__ hin, float4* __restrict__ hout) {
    int v = blockIdx.x;
    int t = threadIdx.x;                 // 0..127
    int b = g_rp[v], e2 = g_rp[v + 1];
    float4 acc = make_float4(0.f, 0.f, 0.f, 0.f);
    #pragma unroll 4
    for (int i = b; i < e2; i++) {
        int2 ed = __ldg(&g_edge[i]);
        float w = __int_as_float(ed.y);
        float4 hv = __ldg(hin + (size_t)ed.x * F4 + t);
        acc.x = fmaf(w, hv.x, acc.x);
        acc.y = fmaf(w, hv.y, acc.y);
        acc.z = fmaf(w, hv.z, acc.z);
        acc.w = fmaf(w, hv.w, acc.w);
    }
    float cs = (1.f - DT) + DT * g_ewself[v];
    float4 h0 = __ldg(hin + (size_t)v * F4 + t);
    float4 o;
    o.x = cs * h0.x + DT * acc.x;
    o.y = cs * h0.y + DT * acc.y;
    o.z = cs * h0.z + DT * acc.z;
    o.w = cs * h0.w + DT * acc.w;
    hout[(size_t)v * F4 + t] = o;
}

// ---------------- packed-f32x2 SGEMM: C[M,512] = A[M,512] * B[512,512]^T ----------------
__device__ __forceinline__ unsigned long long splat2(float a) {
    unsigned long long r;
    asm("mov.b64 %0, {%1, %1};" : "=l"(r) : "r"(__float_as_uint(a)));
    return r;
}
__device__ __forceinline__ void fma2(unsigned long long& c,
                                     unsigned long long a, unsigned long long b) {
    asm("fma.rn.f32x2 %0, %1, %2, %3;" : "=l"(c) : "l"(a), "l"(b), "l"(c));
}
__device__ __forceinline__ float f2lo(unsigned long long v) {
    return __uint_as_float((unsigned)(v & 0xffffffffull));
}
__device__ __forceinline__ float f2hi(unsigned long long v) {
    return __uint_as_float((unsigned)(v >> 32));
}

// MODE 0: C = relu(A*B^T + X[bias])     (X is bias[512])
// MODE 1: C = A*B^T + X[m][n]           (X is [M,512] addend)
template <int MODE>
__global__ __launch_bounds__(256)
void k_gemm(const float* __restrict__ A, const float* __restrict__ B,
            const float* __restrict__ X, float* __restrict__ C, int M) {
    __shared__ float As[2][8][128];
    __shared__ float Bs[2][8][128];

    int tid = threadIdx.x;
    int tx = tid & 15;          // 16 col groups
    int ty = tid >> 4;          // 16 row groups (8 rows each)
    int m0 = blockIdx.y * 128;
    int n0 = blockIdx.x * 128;

    int lrow = tid >> 1;        // 0..127
    int lk = (tid & 1) * 4;     // 0 or 4
    bool arow_ok = (m0 + lrow) < M;
    const float* Aload = A + (size_t)(m0 + lrow) * FDIM + lk;
    const float* Bload = B + (size_t)(n0 + lrow) * FDIM + lk;

    float4 ar = arow_ok ? *(const float4*)Aload : make_float4(0, 0, 0, 0);
    float4 br = *(const float4*)Bload;
    As[0][lk + 0][lrow] = ar.x; As[0][lk + 1][lrow] = ar.y;
    As[0][lk + 2][lrow] = ar.z; As[0][lk + 3][lrow] = ar.w;
    Bs[0][lk + 0][lrow] = br.x; Bs[0][lk + 1][lrow] = br.y;
    Bs[0][lk + 2][lrow] = br.z; Bs[0][lk + 3][lrow] = br.w;
    __syncthreads();

    unsigned long long acc[8][4];
    #pragma unroll
    for (int i = 0; i < 8; i++)
        #pragma unroll
        for (int j = 0; j < 4; j++) acc[i][j] = 0ull;

    const int nk = FDIM / 8;    // 64 K-tiles
    for (int kt = 0; kt < nk; kt++) {
        int cur = kt & 1, nxt = cur ^ 1;
        if (kt + 1 < nk) {
            ar = arow_ok ? *(const float4*)(Aload + (kt + 1) * 8) : make_float4(0, 0, 0, 0);
            br = *(const float4*)(Bload + (kt + 1) * 8);
        }
        #pragma unroll
        for (int kk = 0; kk < 8; kk++) {
            float a[8];
            *(float4*)(a)     = *(const float4*)&As[cur][kk][ty * 8];
            *(float4*)(a + 4) = *(const float4*)&As[cur][kk][ty * 8 + 4];
            // b as packed f32x2 pairs: cols n0+tx*4..+3 and n0+64+tx*4..+3
            ulonglong2 bp0 = *(const ulonglong2*)&Bs[cur][kk][tx * 4];
            ulonglong2 bp1 = *(const ulonglong2*)&Bs[cur][kk][64 + tx * 4];
            unsigned long long b2[4] = { bp0.x, bp0.y, bp1.x, bp1.y };
            #pragma unroll
            for (int i = 0; i < 8; i++) {
                unsigned long long aa = splat2(a[i]);
                fma2(acc[i][0], aa, b2[0]);
                fma2(acc[i][1], aa, b2[1]);
                fma2(acc[i][2], aa, b2[2]);
                fma2(acc[i][3], aa, b2[3]);
            }
        }
        if (kt + 1 < nk) {
            As[nxt][lk + 0][lrow] = ar.x; As[nxt][lk + 1][lrow] = ar.y;
            As[nxt][lk + 2][lrow] = ar.z; As[nxt][lk + 3][lrow] = ar.w;
            Bs[nxt][lk + 0][lrow] = br.x; Bs[nxt][lk + 1][lrow] = br.y;
            Bs[nxt][lk + 2][lrow] = br.z; Bs[nxt][lk + 3][lrow] = br.w;
        }
        __syncthreads();
    }

    int n1 = n0 + tx * 4;
    int n2 = n0 + 64 + tx * 4;
    float4 bias1, bias2;
    if (MODE == 0) {
        bias1 = *(const float4*)&X[n1];
        bias2 = *(const float4*)&X[n2];
    }
    #pragma unroll
    for (int i = 0; i < 8; i++) {
        int m = m0 + ty * 8 + i;
        if (m >= M) break;
        float o[8];
        o[0] = f2lo(acc[i][0]); o[1] = f2hi(acc[i][0]);
        o[2] = f2lo(acc[i][1]); o[3] = f2hi(acc[i][1]);
        o[4] = f2lo(acc[i][2]); o[5] = f2hi(acc[i][2]);
        o[6] = f2lo(acc[i][3]); o[7] = f2hi(acc[i][3]);
        if (MODE == 0) {
            o[0] = fmaxf(o[0] + bias1.x, 0.f); o[1] = fmaxf(o[1] + bias1.y, 0.f);
            o[2] = fmaxf(o[2] + bias1.z, 0.f); o[3] = fmaxf(o[3] + bias1.w, 0.f);
            o[4] = fmaxf(o[4] + bias2.x, 0.f); o[5] = fmaxf(o[5] + bias2.y, 0.f);
            o[6] = fmaxf(o[6] + bias2.z, 0.f); o[7] = fmaxf(o[7] + bias2.w, 0.f);
        } else {
            float4 a1 = *(const float4*)&X[(size_t)m * FDIM + n1];
            float4 a2 = *(const float4*)&X[(size_t)m * FDIM + n2];
            o[0] += a1.x; o[1] += a1.y; o[2] += a1.z; o[3] += a1.w;
            o[4] += a2.x; o[5] += a2.y; o[6] += a2.z; o[7] += a2.w;
        }
        *(float4*)&C[(size_t)m * FDIM + n1] = make_float4(o[0], o[1], o[2], o[3]);
        *(float4*)&C[(size_t)m * FDIM + n2] = make_float4(o[4], o[5], o[6], o[7]);
    }
}

// ---------------- row layernorm, in place ----------------
__global__ void k_ln(float* __restrict__ io, const float* __restrict__ gamma,
                     const float* __restrict__ beta) {
    int r = blockIdx.x;
    int t = threadIdx.x;   // 128
    float4* row = ((float4*)io) + (size_t)r * F4;
    float4 v = row[t];
    float s = v.x + v.y + v.z + v.w;
    float q = v.x * v.x + v.y * v.y + v.z * v.z + v.w * v.w;
    #pragma unroll
    for (int off = 16; off; off >>= 1) {
        s += __shfl_xor_sync(0xffffffffu, s, off);
        q += __shfl_xor_sync(0xffffffffu, q, off);
    }
    __shared__ float ss[4], sq[4];
    if ((t & 31) == 0) { ss[t >> 5] = s; sq[t >> 5] = q; }
    __syncthreads();
    s = ss[0] + ss[1] + ss[2] + ss[3];
    q = sq[0] + sq[1] + sq[2] + sq[3];
    float mu = s * (1.f / FDIM);
    float var = q * (1.f / FDIM) - mu * mu;
    float inv = rsqrtf(var + LNEPS);
    float4 g = ((const float4*)gamma)[t];
    float4 bb = ((const float4*)beta)[t];
    v.x = (v.x - mu) * inv * g.x + bb.x;
    v.y = (v.y - mu) * inv * g.y + bb.y;
    v.z = (v.z - mu) * inv * g.z + bb.z;
    v.w = (v.w - mu) * inv * g.w + bb.w;
    row[t] = v;
}

// ---------------- launch ----------------
extern "C" void kernel_launch(void* const* d_in, const int* in_sizes, int n_in,
                              void* d_out, int out_size) {
    const float* x     = (const float*)d_in[0];
    const int*   ei    = (const int*)d_in[1];
    const float* ts    = (const float*)d_in[2];
    const float* Wt    = (const float*)d_in[3];
    const float* bt    = (const float*)d_in[4];
    const float* Wr    = (const float*)d_in[5];
    const float* gamma = (const float*)d_in[6];
    const float* beta  = (const float*)d_in[7];
    const void*  gt    = d_in[8];

    int n = in_sizes[0] / FDIM;
    int e = in_sizes[1] / 2;

    float *h0, *h1;
    cudaGetSymbolAddress((void**)&h0, g_h0);
    cudaGetSymbolAddress((void**)&h1, g_h1);

    const int tb = 256;
    k_init<<<(n + tb - 1) / tb, tb>>>(n);
    k_max<<<256, 256>>>(ts, e, gt);
    k_edge_deg<<<(e + tb - 1) / tb, tb>>>(ei, ts, e);
    k_node<<<(n + tb - 1) / tb, tb>>>(n, gt);
    k_scan<<<1, 1024>>>(n);
    k_scatter<<<(e + tb - 1) / tb, tb>>>(ei, ts, e);

    // 5 Euler diffusion steps (ping-pong), final result lands in h1
    k_diff<<<n, 128>>>((const float4*)x,  (float4*)h1);
    k_diff<<<n, 128>>>((const float4*)h1, (float4*)h0);
    k_diff<<<n, 128>>>((const float4*)h0, (float4*)h1);
    k_diff<<<n, 128>>>((const float4*)h1, (float4*)h0);
    k_diff<<<n, 128>>>((const float4*)h0, (float4*)h1);

    float* out = (float*)d_out;
    dim3 gg(FDIM / 128, (n + 127) / 128);
    k_gemm<0><<<gg, 256>>>(h1, Wt, bt, h0, n);   // tmp(h0) = relu(h@Wt^T + b)
    k_gemm<1><<<gg, 256>>>(x,  Wr, h0, out, n);  // out = x@Wr^T + tmp
    k_ln<<<n, 128>>>(out, gamma, beta);
}

// round 5
// speedup vs baseline: 1.0995x; 1.0995x over previous
#include <cuda_runtime.h>
#include <math.h>
#include <stdint.h>

#define FDIM 512
#define F4   128
#define NMAX 20608
#define EMAX 335872
#define TDK  0.1f
#define DT   0.2f
#define LNEPS 1e-5f

// ---------------- device scratch ----------------
__device__ float g_h0[(size_t)NMAX * FDIM];
__device__ float g_h1[(size_t)NMAX * FDIM];
__device__ float g_dinv[NMAX];
__device__ float g_ewself[NMAX];
__device__ int   g_cnt[NMAX];
__device__ int   g_cur[NMAX];
__device__ int   g_rp[NMAX + 1];
__device__ int2  g_edge[EMAX];
__device__ int   g_tmaxbits;   // ts > 0, monotonic, idempotent across replays

__device__ __forceinline__ float decode_scalar(const void* p) {
    int iv = *(const int*)p;
    float fv = __int_as_float(iv);
    float fa = fabsf(fv);
    if (isfinite(fv) && fa >= 1e-3f && fa <= 1e9f) return fv;
    return (float)iv;
}

// ---------------- prep ----------------
__global__ void k_prep(const float* __restrict__ ts, int e, int n, const void* gt) {
    int i = blockIdx.x * blockDim.x + threadIdx.x;
    if (i < n) { g_dinv[i] = 0.f; g_cnt[i] = 0; g_cur[i] = 0; }
    float m = -1.f;
    for (int k = i; k < e; k += gridDim.x * blockDim.x) m = fmaxf(m, ts[k]);
    if (i == 0) m = fmaxf(m, decode_scalar(gt));
    #pragma unroll
    for (int off = 16; off; off >>= 1)
        m = fmaxf(m, __shfl_xor_sync(0xffffffffu, m, off));
    if ((threadIdx.x & 31) == 0)
        atomicMax(&g_tmaxbits, __float_as_int(m));
}

__global__ void k_edge_deg(const int* __restrict__ ei, const float* __restrict__ ts, int e) {
    int i = blockIdx.x * blockDim.x + threadIdx.x;
    if (i >= e) return;
    float tmax = __int_as_float(g_tmaxbits);
    int dst = ei[e + i];
    float w = expf(-TDK * (tmax - ts[i]));
    atomicAdd(&g_dinv[dst], w);
    atomicAdd(&g_cnt[dst], 1);
}

__global__ void k_node(int n, const void* gt) {
    int v = blockIdx.x * blockDim.x + threadIdx.x;
    if (v >= n) return;
    float tmax = __int_as_float(g_tmaxbits);
    float ws = expf(-TDK * (tmax - decode_scalar(gt)));
    float d = g_dinv[v] + ws;
    float di = (d > 0.f) ? rsqrtf(d) : 0.f;
    g_dinv[v] = di;
    g_ewself[v] = di * di * ws;
}

__global__ void k_scan(int n) {
    __shared__ int s[1024];
    __shared__ int s_carry;
    int tid = threadIdx.x;
    if (tid == 0) s_carry = 0;
    __syncthreads();
    for (int base = 0; base < n; base += 1024) {
        int i = base + tid;
        int v = (i < n) ? g_cnt[i] : 0;
        s[tid] = v;
        __syncthreads();
        #pragma unroll
        for (int off = 1; off < 1024; off <<= 1) {
            int t = (tid >= off) ? s[tid - off] : 0;
            __syncthreads();
            s[tid] += t;
            __syncthreads();
        }
        int carry = s_carry;
        int tot = s[1023];
        __syncthreads();
        if (i < n) g_rp[i] = carry + s[tid] - v;
        if (tid == 0) s_carry = carry + tot;
        __syncthreads();
    }
    if (tid == 0) g_rp[n] = s_carry;
}

__global__ void k_scatter(const int* __restrict__ ei, const float* __restrict__ ts, int e) {
    int i = blockIdx.x * blockDim.x + threadIdx.x;
    if (i >= e) return;
    float tmax = __int_as_float(g_tmaxbits);
    int src = ei[i];
    int dst = ei[e + i];
    float w = expf(-TDK * (tmax - ts[i]));
    int pos = g_rp[dst] + atomicAdd(&g_cur[dst], 1);
    g_edge[pos] = make_int2(src, __float_as_int(g_dinv[src] * w * g_dinv[dst]));
}

// ---------------- diffusion ----------------
__global__ void k_diff(const float4* __restrict__ hin, float4* __restrict__ hout) {
    int v = blockIdx.x;
    int t = threadIdx.x;
    int b = g_rp[v], e2 = g_rp[v + 1];
    float4 acc = make_float4(0.f, 0.f, 0.f, 0.f);
    #pragma unroll 4
    for (int i = b; i < e2; i++) {
        int2 ed = __ldg(&g_edge[i]);
        float w = __int_as_float(ed.y);
        float4 hv = __ldg(hin + (size_t)ed.x * F4 + t);
        acc.x = fmaf(w, hv.x, acc.x);
        acc.y = fmaf(w, hv.y, acc.y);
        acc.z = fmaf(w, hv.z, acc.z);
        acc.w = fmaf(w, hv.w, acc.w);
    }
    float cs = (1.f - DT) + DT * g_ewself[v];
    float4 h0 = __ldg(hin + (size_t)v * F4 + t);
    float4 o;
    o.x = cs * h0.x + DT * acc.x;
    o.y = cs * h0.y + DT * acc.y;
    o.z = cs * h0.z + DT * acc.z;
    o.w = cs * h0.w + DT * acc.w;
    hout[(size_t)v * F4 + t] = o;
}

// ================= mma.sync tf32 3-pass SGEMM =================
// C[M,512] = A[M,512] * B[512,512]^T  (+ epilogue per MODE)
// Block tile 128x128, 8 warps (2M x 4N), warp tile 64x32 = 4x4 m16n8k8.
// K-chunk 16, double-buffered SMEM, rows padded to 20 floats (conflict-free).

#define KCH   16
#define SPAD  20
#define STAGE (4 * 128 * SPAD)       // floats per stage (Ahi,Alo,Bhi,Blo)
#define SMEMB (2 * STAGE * 4)        // bytes = 81920

__device__ __forceinline__ void cvt_split(float v, float& hi, float& lo) {
    uint32_t h;
    asm("cvt.rna.tf32.f32 %0, %1;" : "=r"(h) : "f"(v));
    hi = __uint_as_float(h);
    float r = v - hi;
    uint32_t l;
    asm("cvt.rna.tf32.f32 %0, %1;" : "=r"(l) : "f"(r));
    lo = __uint_as_float(l);
}

__device__ __forceinline__ void mma_tf32(float* d, const uint32_t* a, const uint32_t* b) {
    asm volatile(
        "mma.sync.aligned.m16n8k8.row.col.f32.tf32.tf32.f32 "
        "{%0,%1,%2,%3}, {%4,%5,%6,%7}, {%8,%9}, {%0,%1,%2,%3};"
        : "+f"(d[0]), "+f"(d[1]), "+f"(d[2]), "+f"(d[3])
        : "r"(a[0]), "r"(a[1]), "r"(a[2]), "r"(a[3]), "r"(b[0]), "r"(b[1]));
}

// MODE 0: C = relu(A*B^T + bias[n])
// MODE 1: C = A*B^T + X[m][n]
template <int MODE>
__global__ __launch_bounds__(256, 1)
void k_gemm_mma(const float* __restrict__ A, const float* __restrict__ B,
                const float* __restrict__ X, float* __restrict__ C, int M) {
    extern __shared__ float sm[];
    int tid = threadIdx.x;
    int lane = tid & 31, wid = tid >> 5;
    int warpM = wid >> 2;                 // 0..1 (64 rows each)
    int warpN = wid & 3;                  // 0..3 (32 cols each)
    int g = lane >> 2, t = lane & 3;
    int m0 = blockIdx.y * 128;
    int n0 = blockIdx.x * 128;

    // GMEM staging mapping: thread -> row lr, col half lc
    int lr = tid >> 1;
    int lc = (tid & 1) * 8;
    bool arow_ok = (m0 + lr) < M;
    const float* Ap = A + (size_t)(m0 + lr) * FDIM + lc;
    const float* Bp = B + (size_t)(n0 + lr) * FDIM + lc;

    float acc[4][4][4];
    #pragma unroll
    for (int i = 0; i < 4; i++)
        #pragma unroll
        for (int j = 0; j < 4; j++)
            #pragma unroll
            for (int k = 0; k < 4; k++) acc[i][j][k] = 0.f;

    float4 pa0, pa1, pb0, pb1;
    // preload chunk 0
    pa0 = arow_ok ? *(const float4*)(Ap)     : make_float4(0, 0, 0, 0);
    pa1 = arow_ok ? *(const float4*)(Ap + 4) : make_float4(0, 0, 0, 0);
    pb0 = *(const float4*)(Bp);
    pb1 = *(const float4*)(Bp + 4);

    // convert+store chunk 0 into stage 0
    {
        float* Ah = sm;
        float* Al = sm + 128 * SPAD;
        float* Bh = sm + 2 * 128 * SPAD;
        float* Bl = sm + 3 * 128 * SPAD;
        float4 h, l;
        int base = lr * SPAD + lc;
        cvt_split(pa0.x, h.x, l.x); cvt_split(pa0.y, h.y, l.y);
        cvt_split(pa0.z, h.z, l.z); cvt_split(pa0.w, h.w, l.w);
        *(float4*)(Ah + base) = h; *(float4*)(Al + base) = l;
        cvt_split(pa1.x, h.x, l.x); cvt_split(pa1.y, h.y, l.y);
        cvt_split(pa1.z, h.z, l.z); cvt_split(pa1.w, h.w, l.w);
        *(float4*)(Ah + base + 4) = h; *(float4*)(Al + base + 4) = l;
        cvt_split(pb0.x, h.x, l.x); cvt_split(pb0.y, h.y, l.y);
        cvt_split(pb0.z, h.z, l.z); cvt_split(pb0.w, h.w, l.w);
        *(float4*)(Bh + base) = h; *(float4*)(Bl + base) = l;
        cvt_split(pb1.x, h.x, l.x); cvt_split(pb1.y, h.y, l.y);
        cvt_split(pb1.z, h.z, l.z); cvt_split(pb1.w, h.w, l.w);
        *(float4*)(Bh + base + 4) = h; *(float4*)(Bl + base + 4) = l;
    }
    __syncthreads();

    const int NKC = FDIM / KCH;  // 32
    for (int kc = 0; kc < NKC; kc++) {
        int cur = kc & 1;
        if (kc + 1 < NKC) {
            const float* Ap2 = Ap + (kc + 1) * KCH;
            const float* Bp2 = Bp + (kc + 1) * KCH;
            pa0 = arow_ok ? *(const float4*)(Ap2)     : make_float4(0, 0, 0, 0);
            pa1 = arow_ok ? *(const float4*)(Ap2 + 4) : make_float4(0, 0, 0, 0);
            pb0 = *(const float4*)(Bp2);
            pb1 = *(const float4*)(Bp2 + 4);
        }

        // compute on stage cur
        {
            const uint32_t* As = (const uint32_t*)(sm + cur * STAGE);
            const uint32_t* Als = As + 128 * SPAD;
            const uint32_t* Bs = As + 2 * 128 * SPAD;
            const uint32_t* Bls = As + 3 * 128 * SPAD;
            int arow = warpM * 64 + g;
            int bn = warpN * 32 + g;
            #pragma unroll
            for (int s = 0; s < 2; s++) {
                int kb = s * 8 + t;
                uint32_t ah[4][4], al[4][4], bh[4][2], bl[4][2];
                #pragma unroll
                for (int mt = 0; mt < 4; mt++) {
                    int b0 = (arow + mt * 16) * SPAD + kb;
                    ah[mt][0] = As[b0];
                    ah[mt][1] = As[b0 + 8 * SPAD];
                    ah[mt][2] = As[b0 + 4];
                    ah[mt][3] = As[b0 + 8 * SPAD + 4];
                    al[mt][0] = Als[b0];
                    al[mt][1] = Als[b0 + 8 * SPAD];
                    al[mt][2] = Als[b0 + 4];
                    al[mt][3] = Als[b0 + 8 * SPAD + 4];
                }
                #pragma unroll
                for (int nt = 0; nt < 4; nt++) {
                    int b0 = (bn + nt * 8) * SPAD + kb;
                    bh[nt][0] = Bs[b0];
                    bh[nt][1] = Bs[b0 + 4];
                    bl[nt][0] = Bls[b0];
                    bl[nt][1] = Bls[b0 + 4];
                }
                #pragma unroll
                for (int mt = 0; mt < 4; mt++)
                    #pragma unroll
                    for (int nt = 0; nt < 4; nt++) {
                        mma_tf32(acc[mt][nt], ah[mt], bh[nt]);
                        mma_tf32(acc[mt][nt], ah[mt], bl[nt]);
                        mma_tf32(acc[mt][nt], al[mt], bh[nt]);
                    }
            }
        }

        // store chunk kc+1 into the other stage
        if (kc + 1 < NKC) {
            float* Ah = sm + (cur ^ 1) * STAGE;
            float* Al = Ah + 128 * SPAD;
            float* Bh = Ah + 2 * 128 * SPAD;
            float* Bl = Ah + 3 * 128 * SPAD;
            float4 h, l;
            int base = lr * SPAD + lc;
            cvt_split(pa0.x, h.x, l.x); cvt_split(pa0.y, h.y, l.y);
            cvt_split(pa0.z, h.z, l.z); cvt_split(pa0.w, h.w, l.w);
            *(float4*)(Ah + base) = h; *(float4*)(Al + base) = l;
            cvt_split(pa1.x, h.x, l.x); cvt_split(pa1.y, h.y, l.y);
            cvt_split(pa1.z, h.z, l.z); cvt_split(pa1.w, h.w, l.w);
            *(float4*)(Ah + base + 4) = h; *(float4*)(Al + base + 4) = l;
            cvt_split(pb0.x, h.x, l.x); cvt_split(pb0.y, h.y, l.y);
            cvt_split(pb0.z, h.z, l.z); cvt_split(pb0.w, h.w, l.w);
            *(float4*)(Bh + base) = h; *(float4*)(Bl + base) = l;
            cvt_split(pb1.x, h.x, l.x); cvt_split(pb1.y, h.y, l.y);
            cvt_split(pb1.z, h.z, l.z); cvt_split(pb1.w, h.w, l.w);
            *(float4*)(Bh + base + 4) = h; *(float4*)(Bl + base + 4) = l;
        }
        __syncthreads();
    }

    // epilogue: c0,c1 -> (row, 2t), (row, 2t+1); c2,c3 -> row+8
    #pragma unroll
    for (int mt = 0; mt < 4; mt++) {
        int row0 = m0 + warpM * 64 + mt * 16 + g;
        #pragma unroll
        for (int half = 0; half < 2; half++) {
            int row = row0 + half * 8;
            if (row >= M) continue;
            #pragma unroll
            for (int nt = 0; nt < 4; nt++) {
                int col = n0 + warpN * 32 + nt * 8 + t * 2;
                float v0 = acc[mt][nt][half * 2 + 0];
                float v1 = acc[mt][nt][half * 2 + 1];
                if (MODE == 0) {
                    float2 bb = *(const float2*)&X[col];
                    v0 = fmaxf(v0 + bb.x, 0.f);
                    v1 = fmaxf(v1 + bb.y, 0.f);
                } else {
                    float2 xx = *(const float2*)&X[(size_t)row * FDIM + col];
                    v0 += xx.x;
                    v1 += xx.y;
                }
                *(float2*)&C[(size_t)row * FDIM + col] = make_float2(v0, v1);
            }
        }
    }
}

// ---------------- layernorm ----------------
__global__ void k_ln(float* __restrict__ io, const float* __restrict__ gamma,
                     const float* __restrict__ beta) {
    int r = blockIdx.x;
    int t = threadIdx.x;
    float4* row = ((float4*)io) + (size_t)r * F4;
    float4 v = row[t];
    float s = v.x + v.y + v.z + v.w;
    float q = v.x * v.x + v.y * v.y + v.z * v.z + v.w * v.w;
    #pragma unroll
    for (int off = 16; off; off >>= 1) {
        s += __shfl_xor_sync(0xffffffffu, s, off);
        q += __shfl_xor_sync(0xffffffffu, q, off);
    }
    __shared__ float ss[4], sq[4];
    if ((t & 31) == 0) { ss[t >> 5] = s; sq[t >> 5] = q; }
    __syncthreads();
    s = ss[0] + ss[1] + ss[2] + ss[3];
    q = sq[0] + sq[1] + sq[2] + sq[3];
    float mu = s * (1.f / FDIM);
    float var = q * (1.f / FDIM) - mu * mu;
    float inv = rsqrtf(var + LNEPS);
    float4 g = ((const float4*)gamma)[t];
    float4 bb = ((const float4*)beta)[t];
    v.x = (v.x - mu) * inv * g.x + bb.x;
    v.y = (v.y - mu) * inv * g.y + bb.y;
    v.z = (v.z - mu) * inv * g.z + bb.z;
    v.w = (v.w - mu) * inv * g.w + bb.w;
    row[t] = v;
}

// ---------------- launch ----------------
extern "C" void kernel_launch(void* const* d_in, const int* in_sizes, int n_in,
                              void* d_out, int out_size) {
    const float* x     = (const float*)d_in[0];
    const int*   ei    = (const int*)d_in[1];
    const float* ts    = (const float*)d_in[2];
    const float* Wt    = (const float*)d_in[3];
    const float* bt    = (const float*)d_in[4];
    const float* Wr    = (const float*)d_in[5];
    const float* gamma = (const float*)d_in[6];
    const float* beta  = (const float*)d_in[7];
    const void*  gt    = d_in[8];

    int n = in_sizes[0] / FDIM;
    int e = in_sizes[1] / 2;

    float *h0, *h1;
    cudaGetSymbolAddress((void**)&h0, g_h0);
    cudaGetSymbolAddress((void**)&h1, g_h1);

    cudaFuncSetAttribute(k_gemm_mma<0>, cudaFuncAttributeMaxDynamicSharedMemorySize, SMEMB);
    cudaFuncSetAttribute(k_gemm_mma<1>, cudaFuncAttributeMaxDynamicSharedMemorySize, SMEMB);

    const int tb = 256;
    k_prep<<<(n + tb - 1) / tb, tb>>>(ts, e, n, gt);
    k_edge_deg<<<(e + tb - 1) / tb, tb>>>(ei, ts, e);
    k_node<<<(n + tb - 1) / tb, tb>>>(n, gt);
    k_scan<<<1, 1024>>>(n);
    k_scatter<<<(e + tb - 1) / tb, tb>>>(ei, ts, e);

    // 5 Euler diffusion steps; result in h1
    k_diff<<<n, 128>>>((const float4*)x,  (float4*)h1);
    k_diff<<<n, 128>>>((const float4*)h1, (float4*)h0);
    k_diff<<<n, 128>>>((const float4*)h0, (float4*)h1);
    k_diff<<<n, 128>>>((const float4*)h1, (float4*)h0);
    k_diff<<<n, 128>>>((const float4*)h0, (float4*)h1);

    float* out = (float*)d_out;
    dim3 gg(FDIM / 128, (n + 127) / 128);   // (4, 157)
    k_gemm_mma<0><<<gg, 256, SMEMB>>>(h1, Wt, bt, h0, n);   // h0 = relu(h@Wt^T + b)
    k_gemm_mma<1><<<gg, 256, SMEMB>>>(x,  Wr, h0, out, n);  // out = x@Wr^T + h0
    k_ln<<<n, 128>>>(out, gamma, beta);
}

// round 6
// speedup vs baseline: 1.8418x; 1.6752x over previous
#include <cuda_runtime.h>
#include <cuda_bf16.h>
#include <math.h>
#include <stdint.h>

#define FDIM 512
#define F4   128
#define NMAX 20608
#define EMAX 335872
#define TDK  0.1f
#define DT   0.2f
#define LNEPS 1e-5f

// ---------------- device scratch ----------------
__device__ float g_h0[(size_t)NMAX * FDIM];
__device__ float g_h1[(size_t)NMAX * FDIM];
__device__ float g_dinv[NMAX];
__device__ float g_ewself[NMAX];
__device__ int   g_cnt[NMAX];
__device__ int   g_cur[NMAX];
__device__ int   g_rp[NMAX + 1];
__device__ int2  g_edge[EMAX];
__device__ int   g_tmaxbits;   // ts > 0, monotonic, idempotent across replays

__device__ __forceinline__ float decode_scalar(const void* p) {
    int iv = *(const int*)p;
    float fv = __int_as_float(iv);
    float fa = fabsf(fv);
    if (isfinite(fv) && fa >= 1e-3f && fa <= 1e9f) return fv;
    return (float)iv;
}

// ---------------- prep ----------------
__global__ void k_prep(const float* __restrict__ ts, int e, int n, const void* gt) {
    int i = blockIdx.x * blockDim.x + threadIdx.x;
    if (i < n) { g_dinv[i] = 0.f; g_cnt[i] = 0; g_cur[i] = 0; }
    float m = -1.f;
    for (int k = i; k < e; k += gridDim.x * blockDim.x) m = fmaxf(m, ts[k]);
    if (i == 0) m = fmaxf(m, decode_scalar(gt));
    #pragma unroll
    for (int off = 16; off; off >>= 1)
        m = fmaxf(m, __shfl_xor_sync(0xffffffffu, m, off));
    if ((threadIdx.x & 31) == 0)
        atomicMax(&g_tmaxbits, __float_as_int(m));
}

__global__ void k_edge_deg(const int* __restrict__ ei, const float* __restrict__ ts, int e) {
    int i = blockIdx.x * blockDim.x + threadIdx.x;
    if (i >= e) return;
    float tmax = __int_as_float(g_tmaxbits);
    int dst = ei[e + i];
    float w = expf(-TDK * (tmax - ts[i]));
    atomicAdd(&g_dinv[dst], w);
    atomicAdd(&g_cnt[dst], 1);
}

__global__ void k_node(int n, const void* gt) {
    int v = blockIdx.x * blockDim.x + threadIdx.x;
    if (v >= n) return;
    float tmax = __int_as_float(g_tmaxbits);
    float ws = expf(-TDK * (tmax - decode_scalar(gt)));
    float d = g_dinv[v] + ws;
    float di = (d > 0.f) ? rsqrtf(d) : 0.f;
    g_dinv[v] = di;
    g_ewself[v] = di * di * ws;
}

// fast single-block scan: each thread owns a contiguous segment
__global__ void k_scan(int n) {
    __shared__ int wsum[32];
    int tid = threadIdx.x;
    int ch = (n + 1023) >> 10;
    int beg = tid * ch;
    int end = min(beg + ch, n);
    int s = 0;
    for (int i = beg; i < end; i++) s += g_cnt[i];
    int lane = tid & 31, w = tid >> 5;
    int inc = s;
    #pragma unroll
    for (int o = 1; o < 32; o <<= 1) {
        int v = __shfl_up_sync(0xffffffffu, inc, o);
        if (lane >= o) inc += v;
    }
    if (lane == 31) wsum[w] = inc;
    __syncthreads();
    if (w == 0) {
        int v = wsum[lane];
        int wi = v;
        #pragma unroll
        for (int o = 1; o < 32; o <<= 1) {
            int u = __shfl_up_sync(0xffffffffu, wi, o);
            if (lane >= o) wi += u;
        }
        wsum[lane] = wi - v;   // exclusive warp offsets
    }
    __syncthreads();
    int excl = wsum[w] + inc - s;
    int run = excl;
    for (int i = beg; i < end; i++) {
        int c = g_cnt[i];
        g_rp[i] = run;
        run += c;
    }
    if (tid == 1023) g_rp[n] = excl + s;
}

__global__ void k_scatter(const int* __restrict__ ei, const float* __restrict__ ts, int e) {
    int i = blockIdx.x * blockDim.x + threadIdx.x;
    if (i >= e) return;
    float tmax = __int_as_float(g_tmaxbits);
    int src = ei[i];
    int dst = ei[e + i];
    float w = expf(-TDK * (tmax - ts[i]));
    int pos = g_rp[dst] + atomicAdd(&g_cur[dst], 1);
    g_edge[pos] = make_int2(src, __float_as_int(g_dinv[src] * w * g_dinv[dst]));
}

// ---------------- diffusion: smem-staged edge list ----------------
__global__ void k_diff(const float4* __restrict__ hin, float4* __restrict__ hout) {
    __shared__ int2 se[64];
    int v = blockIdx.x;
    int t = threadIdx.x;                 // 128
    int b = g_rp[v], e2 = g_rp[v + 1];
    float4 acc = make_float4(0.f, 0.f, 0.f, 0.f);
    for (int c = b; c < e2; c += 64) {
        int m = min(64, e2 - c);
        __syncthreads();
        if (t < m) se[t] = __ldg(&g_edge[c + t]);
        __syncthreads();
        #pragma unroll 4
        for (int i = 0; i < m; i++) {
            int2 ed = se[i];
            float w = __int_as_float(ed.y);
            float4 hv = __ldg(hin + (size_t)ed.x * F4 + t);
            acc.x = fmaf(w, hv.x, acc.x);
            acc.y = fmaf(w, hv.y, acc.y);
            acc.z = fmaf(w, hv.z, acc.z);
            acc.w = fmaf(w, hv.w, acc.w);
        }
    }
    float cs = (1.f - DT) + DT * g_ewself[v];
    float4 h0 = __ldg(hin + (size_t)v * F4 + t);
    float4 o;
    o.x = cs * h0.x + DT * acc.x;
    o.y = cs * h0.y + DT * acc.y;
    o.z = cs * h0.z + DT * acc.z;
    o.w = cs * h0.w + DT * acc.w;
    hout[(size_t)v * F4 + t] = o;
}

// ================= mma.sync bf16 split SGEMM =================
// C[M,512] = A[M,512] * B[512,512]^T  (+ epilogue per MODE)
// v = b1 + b2 (bf16 each); A*B ~= a1b1 + a1b2 + a2b1 (err ~2^-18).
// Block 128x128, 8 warps (2M x 4N), warp 64x32 = 4x4 m16n8k16 tiles.
// K-chunk 16, double-buffered. SMEM rows: 8 bf16x2 words + 1 pad = stride 9.

#define KCH    16
#define RSTR   9                      // u32 words per row (8 + pad)
#define ARR    (128 * RSTR)           // words per array
#define STAGEW (4 * ARR)              // A1,A2,B1,B2
#define SMEMB  (2 * STAGEW * 4)       // 36864 bytes

__device__ __forceinline__ uint32_t bsplit2(float x, float y, uint32_t& t2) {
    __nv_bfloat16 hx = __float2bfloat16_rn(x);
    __nv_bfloat16 hy = __float2bfloat16_rn(y);
    float rx = x - __bfloat162float(hx);
    float ry = y - __bfloat162float(hy);
    __nv_bfloat16 lx = __float2bfloat16_rn(rx);
    __nv_bfloat16 ly = __float2bfloat16_rn(ry);
    t2 = (uint32_t)__bfloat16_as_ushort(lx) | ((uint32_t)__bfloat16_as_ushort(ly) << 16);
    return (uint32_t)__bfloat16_as_ushort(hx) | ((uint32_t)__bfloat16_as_ushort(hy) << 16);
}

__device__ __forceinline__ void mma_bf16(float* d, const uint32_t* a, const uint32_t* b) {
    asm volatile(
        "mma.sync.aligned.m16n8k16.row.col.f32.bf16.bf16.f32 "
        "{%0,%1,%2,%3}, {%4,%5,%6,%7}, {%8,%9}, {%0,%1,%2,%3};"
        : "+f"(d[0]), "+f"(d[1]), "+f"(d[2]), "+f"(d[3])
        : "r"(a[0]), "r"(a[1]), "r"(a[2]), "r"(a[3]), "r"(b[0]), "r"(b[1]));
}

// stage one K-chunk (this thread's 8 floats of A and of B) into SMEM arrays
__device__ __forceinline__ void stage_chunk(uint32_t* S, int wb,
                                            float4 pa0, float4 pa1,
                                            float4 pb0, float4 pb1) {
    uint32_t* A1 = S;
    uint32_t* A2 = S + ARR;
    uint32_t* B1 = S + 2 * ARR;
    uint32_t* B2 = S + 3 * ARR;
    uint32_t t2;
    A1[wb + 0] = bsplit2(pa0.x, pa0.y, t2); A2[wb + 0] = t2;
    A1[wb + 1] = bsplit2(pa0.z, pa0.w, t2); A2[wb + 1] = t2;
    A1[wb + 2] = bsplit2(pa1.x, pa1.y, t2); A2[wb + 2] = t2;
    A1[wb + 3] = bsplit2(pa1.z, pa1.w, t2); A2[wb + 3] = t2;
    B1[wb + 0] = bsplit2(pb0.x, pb0.y, t2); B2[wb + 0] = t2;
    B1[wb + 1] = bsplit2(pb0.z, pb0.w, t2); B2[wb + 1] = t2;
    B1[wb + 2] = bsplit2(pb1.x, pb1.y, t2); B2[wb + 2] = t2;
    B1[wb + 3] = bsplit2(pb1.z, pb1.w, t2); B2[wb + 3] = t2;
}

// MODE 0: C = relu(A*B^T + bias[n]);  MODE 1: C = A*B^T + X[m][n]
template <int MODE>
__global__ __launch_bounds__(256, 1)
void k_gemm_mma(const float* __restrict__ A, const float* __restrict__ B,
                const float* __restrict__ X, float* __restrict__ C, int M) {
    extern __shared__ uint32_t smu[];
    int tid = threadIdx.x;
    int lane = tid & 31, wid = tid >> 5;
    int warpM = wid >> 2;
    int warpN = wid & 3;
    int g = lane >> 2, t = lane & 3;
    int m0 = blockIdx.y * 128;
    int n0 = blockIdx.x * 128;

    int lr = tid >> 1;
    int lc = (tid & 1) * 8;             // k offset within chunk
    int wb = lr * RSTR + (tid & 1) * 4; // word base for staging
    bool arow_ok = (m0 + lr) < M;
    const float* Ap = A + (size_t)(m0 + lr) * FDIM + lc;
    const float* Bp = B + (size_t)(n0 + lr) * FDIM + lc;

    float acc[4][4][4];
    #pragma unroll
    for (int i = 0; i < 4; i++)
        #pragma unroll
        for (int j = 0; j < 4; j++)
            #pragma unroll
            for (int k = 0; k < 4; k++) acc[i][j][k] = 0.f;

    float4 pa0, pa1, pb0, pb1;
    pa0 = arow_ok ? *(const float4*)(Ap)     : make_float4(0, 0, 0, 0);
    pa1 = arow_ok ? *(const float4*)(Ap + 4) : make_float4(0, 0, 0, 0);
    pb0 = *(const float4*)(Bp);
    pb1 = *(const float4*)(Bp + 4);
    stage_chunk(smu, wb, pa0, pa1, pb0, pb1);
    __syncthreads();

    const int NKC = FDIM / KCH;   // 32
    for (int kc = 0; kc < NKC; kc++) {
        int cur = kc & 1;
        if (kc + 1 < NKC) {
            const float* Ap2 = Ap + (kc + 1) * KCH;
            const float* Bp2 = Bp + (kc + 1) * KCH;
            pa0 = arow_ok ? *(const float4*)(Ap2)     : make_float4(0, 0, 0, 0);
            pa1 = arow_ok ? *(const float4*)(Ap2 + 4) : make_float4(0, 0, 0, 0);
            pb0 = *(const float4*)(Bp2);
            pb1 = *(const float4*)(Bp2 + 4);
        }

        {
            const uint32_t* S  = smu + cur * STAGEW;
            const uint32_t* A1 = S;
            const uint32_t* A2 = S + ARR;
            const uint32_t* B1 = S + 2 * ARR;
            const uint32_t* B2 = S + 3 * ARR;
            int arow = warpM * 64 + g;
            int bn = warpN * 32 + g;
            uint32_t a1[4][4], a2[4][4], b1[4][2], b2[4][2];
            #pragma unroll
            for (int mt = 0; mt < 4; mt++) {
                int r0 = (arow + mt * 16) * RSTR;
                int r8 = r0 + 8 * RSTR;
                a1[mt][0] = A1[r0 + t];     a1[mt][1] = A1[r8 + t];
                a1[mt][2] = A1[r0 + t + 4]; a1[mt][3] = A1[r8 + t + 4];
                a2[mt][0] = A2[r0 + t];     a2[mt][1] = A2[r8 + t];
                a2[mt][2] = A2[r0 + t + 4]; a2[mt][3] = A2[r8 + t + 4];
            }
            #pragma unroll
            for (int nt = 0; nt < 4; nt++) {
                int r0 = (bn + nt * 8) * RSTR;
                b1[nt][0] = B1[r0 + t]; b1[nt][1] = B1[r0 + t + 4];
                b2[nt][0] = B2[r0 + t]; b2[nt][1] = B2[r0 + t + 4];
            }
            #pragma unroll
            for (int mt = 0; mt < 4; mt++)
                #pragma unroll
                for (int nt = 0; nt < 4; nt++) {
                    mma_bf16(acc[mt][nt], a1[mt], b1[nt]);
                    mma_bf16(acc[mt][nt], a1[mt], b2[nt]);
                    mma_bf16(acc[mt][nt], a2[mt], b1[nt]);
                }
        }

        if (kc + 1 < NKC)
            stage_chunk(smu + (cur ^ 1) * STAGEW, wb, pa0, pa1, pb0, pb1);
        __syncthreads();
    }

    #pragma unroll
    for (int mt = 0; mt < 4; mt++) {
        int row0 = m0 + warpM * 64 + mt * 16 + g;
        #pragma unroll
        for (int half = 0; half < 2; half++) {
            int row = row0 + half * 8;
            if (row >= M) continue;
            #pragma unroll
            for (int nt = 0; nt < 4; nt++) {
                int col = n0 + warpN * 32 + nt * 8 + t * 2;
                float v0 = acc[mt][nt][half * 2 + 0];
                float v1 = acc[mt][nt][half * 2 + 1];
                if (MODE == 0) {
                    float2 bb = *(const float2*)&X[col];
                    v0 = fmaxf(v0 + bb.x, 0.f);
                    v1 = fmaxf(v1 + bb.y, 0.f);
                } else {
                    float2 xx = *(const float2*)&X[(size_t)row * FDIM + col];
                    v0 += xx.x;
                    v1 += xx.y;
                }
                *(float2*)&C[(size_t)row * FDIM + col] = make_float2(v0, v1);
            }
        }
    }
}

// ---------------- layernorm ----------------
__global__ void k_ln(float* __restrict__ io, const float* __restrict__ gamma,
                     const float* __restrict__ beta) {
    int r = blockIdx.x;
    int t = threadIdx.x;
    float4* row = ((float4*)io) + (size_t)r * F4;
    float4 v = row[t];
    float s = v.x + v.y + v.z + v.w;
    float q = v.x * v.x + v.y * v.y + v.z * v.z + v.w * v.w;
    #pragma unroll
    for (int off = 16; off; off >>= 1) {
        s += __shfl_xor_sync(0xffffffffu, s, off);
        q += __shfl_xor_sync(0xffffffffu, q, off);
    }
    __shared__ float ss[4], sq[4];
    if ((t & 31) == 0) { ss[t >> 5] = s; sq[t >> 5] = q; }
    __syncthreads();
    s = ss[0] + ss[1] + ss[2] + ss[3];
    q = sq[0] + sq[1] + sq[2] + sq[3];
    float mu = s * (1.f / FDIM);
    float var = q * (1.f / FDIM) - mu * mu;
    float inv = rsqrtf(var + LNEPS);
    float4 g = ((const float4*)gamma)[t];
    float4 bb = ((const float4*)beta)[t];
    v.x = (v.x - mu) * inv * g.x + bb.x;
    v.y = (v.y - mu) * inv * g.y + bb.y;
    v.z = (v.z - mu) * inv * g.z + bb.z;
    v.w = (v.w - mu) * inv * g.w + bb.w;
    row[t] = v;
}

// ---------------- launch ----------------
extern "C" void kernel_launch(void* const* d_in, const int* in_sizes, int n_in,
                              void* d_out, int out_size) {
    const float* x     = (const float*)d_in[0];
    const int*   ei    = (const int*)d_in[1];
    const float* ts    = (const float*)d_in[2];
    const float* Wt    = (const float*)d_in[3];
    const float* bt    = (const float*)d_in[4];
    const float* Wr    = (const float*)d_in[5];
    const float* gamma = (const float*)d_in[6];
    const float* beta  = (const float*)d_in[7];
    const void*  gt    = d_in[8];

    int n = in_sizes[0] / FDIM;
    int e = in_sizes[1] / 2;

    float *h0, *h1;
    cudaGetSymbolAddress((void**)&h0, g_h0);
    cudaGetSymbolAddress((void**)&h1, g_h1);

    cudaFuncSetAttribute(k_gemm_mma<0>, cudaFuncAttributeMaxDynamicSharedMemorySize, SMEMB);
    cudaFuncSetAttribute(k_gemm_mma<1>, cudaFuncAttributeMaxDynamicSharedMemorySize, SMEMB);

    const int tb = 256;
    k_prep<<<(n + tb - 1) / tb, tb>>>(ts, e, n, gt);
    k_edge_deg<<<(e + tb - 1) / tb, tb>>>(ei, ts, e);
    k_node<<<(n + tb - 1) / tb, tb>>>(n, gt);
    k_scan<<<1, 1024>>>(n);
    k_scatter<<<(e + tb - 1) / tb, tb>>>(ei, ts, e);

    // 5 Euler diffusion steps; result in h1
    k_diff<<<n, 128>>>((const float4*)x,  (float4*)h1);
    k_diff<<<n, 128>>>((const float4*)h1, (float4*)h0);
    k_diff<<<n, 128>>>((const float4*)h0, (float4*)h1);
    k_diff<<<n, 128>>>((const float4*)h1, (float4*)h0);
    k_diff<<<n, 128>>>((const float4*)h0, (float4*)h1);

    float* out = (float*)d_out;
    dim3 gg(FDIM / 128, (n + 127) / 128);   // (4, 157)
    k_gemm_mma<0><<<gg, 256, SMEMB>>>(h1, Wt, bt, h0, n);   // h0 = relu(h@Wt^T + b)
    k_gemm_mma<1><<<gg, 256, SMEMB>>>(x,  Wr, h0, out, n);  // out = x@Wr^T + h0
    k_ln<<<n, 128>>>(out, gamma, beta);
}

// round 8
// speedup vs baseline: 2.3379x; 1.2694x over previous
#include <cuda_runtime.h>
#include <cuda_bf16.h>
#include <math.h>
#include <stdint.h>

#define FDIM 512
#define F4   128
#define NMAX 20608
#define EMAX 335872
#define TDK  0.1f
#define DT   0.2f
#define LNEPS 1e-5f

// ---------------- device scratch ----------------
__device__ float g_h0[(size_t)NMAX * FDIM];
__device__ float g_h1[(size_t)NMAX * FDIM];
__device__ uint4 g_ca[(size_t)NMAX * 128];    // split-bf16 h   (512 u32 words/row)
__device__ uint4 g_cx[(size_t)NMAX * 128];    // split-bf16 x
__device__ uint4 g_cwt[512 * 128];            // split-bf16 Wt
__device__ uint4 g_cwr[512 * 128];            // split-bf16 Wr
__device__ float g_dinv[NMAX];
__device__ float g_ewself[NMAX];
__device__ int   g_cnt[NMAX];
__device__ int   g_cur[NMAX];
__device__ int   g_rp[NMAX + 1];
__device__ int2  g_edge[EMAX];
__device__ int   g_tmaxbits;   // ts > 0, monotonic, idempotent across replays

__device__ __forceinline__ float decode_scalar(const void* p) {
    int iv = *(const int*)p;
    float fv = __int_as_float(iv);
    float fa = fabsf(fv);
    if (isfinite(fv) && fa >= 1e-3f && fa <= 1e9f) return fv;
    return (float)iv;
}

// ---------------- prep ----------------
__global__ void k_prep(const float* __restrict__ ts, int e, int n, const void* gt) {
    int i = blockIdx.x * blockDim.x + threadIdx.x;
    if (i < n) { g_dinv[i] = 0.f; g_cnt[i] = 0; g_cur[i] = 0; }
    float m = -1.f;
    for (int k = i; k < e; k += gridDim.x * blockDim.x) m = fmaxf(m, ts[k]);
    if (i == 0) m = fmaxf(m, decode_scalar(gt));
    #pragma unroll
    for (int off = 16; off; off >>= 1)
        m = fmaxf(m, __shfl_xor_sync(0xffffffffu, m, off));
    if ((threadIdx.x & 31) == 0)
        atomicMax(&g_tmaxbits, __float_as_int(m));
}

__global__ void k_edge_deg(const int* __restrict__ ei, const float* __restrict__ ts, int e) {
    int i = blockIdx.x * blockDim.x + threadIdx.x;
    if (i >= e) return;
    float tmax = __int_as_float(g_tmaxbits);
    int dst = ei[e + i];
    float w = expf(-TDK * (tmax - ts[i]));
    atomicAdd(&g_dinv[dst], w);
    atomicAdd(&g_cnt[dst], 1);
}

__global__ void k_node(int n, const void* gt) {
    int v = blockIdx.x * blockDim.x + threadIdx.x;
    if (v >= n) return;
    float tmax = __int_as_float(g_tmaxbits);
    float ws = expf(-TDK * (tmax - decode_scalar(gt)));
    float d = g_dinv[v] + ws;
    float di = (d > 0.f) ? rsqrtf(d) : 0.f;
    g_dinv[v] = di;
    g_ewself[v] = di * di * ws;
}

// fast single-block scan: each thread owns a contiguous segment
__global__ void k_scan(int n) {
    __shared__ int wsum[32];
    int tid = threadIdx.x;
    int ch = (n + 1023) >> 10;
    int beg = tid * ch;
    int end = min(beg + ch, n);
    int s = 0;
    for (int i = beg; i < end; i++) s += g_cnt[i];
    int lane = tid & 31, w = tid >> 5;
    int inc = s;
    #pragma unroll
    for (int o = 1; o < 32; o <<= 1) {
        int v = __shfl_up_sync(0xffffffffu, inc, o);
        if (lane >= o) inc += v;
    }
    if (lane == 31) wsum[w] = inc;
    __syncthreads();
    if (w == 0) {
        int v = wsum[lane];
        int wi = v;
        #pragma unroll
        for (int o = 1; o < 32; o <<= 1) {
            int u = __shfl_up_sync(0xffffffffu, wi, o);
            if (lane >= o) wi += u;
        }
        wsum[lane] = wi - v;
    }
    __syncthreads();
    int excl = wsum[w] + inc - s;
    int run = excl;
    for (int i = beg; i < end; i++) {
        int c = g_cnt[i];
        g_rp[i] = run;
        run += c;
    }
    if (tid == 1023) g_rp[n] = excl + s;
}

__global__ void k_scatter(const int* __restrict__ ei, const float* __restrict__ ts, int e) {
    int i = blockIdx.x * blockDim.x + threadIdx.x;
    if (i >= e) return;
    float tmax = __int_as_float(g_tmaxbits);
    int src = ei[i];
    int dst = ei[e + i];
    float w = expf(-TDK * (tmax - ts[i]));
    int pos = g_rp[dst] + atomicAdd(&g_cur[dst], 1);
    g_edge[pos] = make_int2(src, __float_as_int(g_dinv[src] * w * g_dinv[dst]));
}

// ---------------- diffusion: smem-staged edge list ----------------
__global__ void k_diff(const float4* __restrict__ hin, float4* __restrict__ hout) {
    __shared__ int2 se[64];
    int v = blockIdx.x;
    int t = threadIdx.x;                 // 128
    int b = g_rp[v], e2 = g_rp[v + 1];
    float4 acc = make_float4(0.f, 0.f, 0.f, 0.f);
    for (int c = b; c < e2; c += 64) {
        int m = min(64, e2 - c);
        __syncthreads();
        if (t < m) se[t] = __ldg(&g_edge[c + t]);
        __syncthreads();
        #pragma unroll 4
        for (int i = 0; i < m; i++) {
            int2 ed = se[i];
            float w = __int_as_float(ed.y);
            float4 hv = __ldg(hin + (size_t)ed.x * F4 + t);
            acc.x = fmaf(w, hv.x, acc.x);
            acc.y = fmaf(w, hv.y, acc.y);
            acc.z = fmaf(w, hv.z, acc.z);
            acc.w = fmaf(w, hv.w, acc.w);
        }
    }
    float cs = (1.f - DT) + DT * g_ewself[v];
    float4 h0 = __ldg(hin + (size_t)v * F4 + t);
    float4 o;
    o.x = cs * h0.x + DT * acc.x;
    o.y = cs * h0.y + DT * acc.y;
    o.z = cs * h0.z + DT * acc.z;
    o.w = cs * h0.w + DT * acc.w;
    hout[(size_t)v * F4 + t] = o;
}

// ================= split-bf16 pre-conversion =================
// Layout per row (512 floats): 32 chunks x 16 u32 words.
// Chunk word slots, for t = 0..3:  slot[4t]=hi_t, [4t+1]=hi_{t+4},
//                                  [4t+2]=lo_t, [4t+3]=lo_{t+4}
// where word w packs elements (2w, 2w+1) of the chunk as bf16x2.

__device__ __forceinline__ uint32_t bsplit2(float x, float y, uint32_t& t2) {
    __nv_bfloat16 hx = __float2bfloat16_rn(x);
    __nv_bfloat16 hy = __float2bfloat16_rn(y);
    float rx = x - __bfloat162float(hx);
    float ry = y - __bfloat162float(hy);
    __nv_bfloat16 lx = __float2bfloat16_rn(rx);
    __nv_bfloat16 ly = __float2bfloat16_rn(ry);
    t2 = (uint32_t)__bfloat16_as_ushort(lx) | ((uint32_t)__bfloat16_as_ushort(ly) << 16);
    return (uint32_t)__bfloat16_as_ushort(hx) | ((uint32_t)__bfloat16_as_ushort(hy) << 16);
}

// one thread per (row, chunk, half): total = R * 64 threads
__global__ void k_cvt(const float* __restrict__ in, uint4* __restrict__ out, int total) {
    int idx = blockIdx.x * blockDim.x + threadIdx.x;
    if (idx >= total) return;
    int row = idx >> 6;
    int rem = idx & 63;
    int kc = rem >> 1;
    int h = rem & 1;                      // half: words j=2h, j+1, j+4, j+5
    const float* p = in + (size_t)row * FDIM + kc * 16 + 4 * h;
    float4 v0 = *(const float4*)(p);      // words j, j+1
    float4 v1 = *(const float4*)(p + 8);  // words j+4, j+5
    uint32_t l0, l1, l4, l5;
    uint32_t h0 = bsplit2(v0.x, v0.y, l0);
    uint32_t h1 = bsplit2(v0.z, v0.w, l1);
    uint32_t h4 = bsplit2(v1.x, v1.y, l4);
    uint32_t h5 = bsplit2(v1.z, v1.w, l5);
    size_t ob = (size_t)row * 128 + kc * 4 + 2 * h;     // uint4 units
    out[ob]     = make_uint4(h0, h4, l0, l4);   // slots 8h+0..3
    out[ob + 1] = make_uint4(h1, h5, l1, l5);   // slots 8h+4..7
}

// ================= mma.sync bf16 split SGEMM (pre-converted inputs) ========
// C[M,512] = A[M,512] * B[512,512]^T; 3 products a1b1+a1b2+a2b1.
// Block 128x128, 8 warps (2M x 4N), warp 64x32 = 4x4 m16n8k16 tiles.
// 3-stage cp.async pipeline; SMEM: 3 stages x (A 8KB + B 8KB) = 48KB dynamic.

#define NKC   32
#define SMEMB 49152
#define SB(s, mat, row, q) sbuf[((((s) * 2 + (mat)) * 128 + (row)) << 2) + (q)]

__device__ __forceinline__ uint32_t smem_u32(const void* p) {
    uint32_t a;
    asm("{ .reg .u64 t; cvta.to.shared.u64 t, %1; cvt.u32.u64 %0, t; }" : "=r"(a) : "l"(p));
    return a;
}
__device__ __forceinline__ void cp16(uint32_t d, const void* s) {
    asm volatile("cp.async.ca.shared.global [%0], [%1], 16;" :: "r"(d), "l"(s));
}
__device__ __forceinline__ void cp_commit() {
    asm volatile("cp.async.commit_group;" ::: "memory");
}
__device__ __forceinline__ void cp_wait1() {
    asm volatile("cp.async.wait_group 1;" ::: "memory");
}
__device__ __forceinline__ void cp_wait0() {
    asm volatile("cp.async.wait_group 0;" ::: "memory");
}

__device__ __forceinline__ void mma_bf16(float* d, const uint32_t* a, const uint32_t* b) {
    asm volatile(
        "mma.sync.aligned.m16n8k16.row.col.f32.bf16.bf16.f32 "
        "{%0,%1,%2,%3}, {%4,%5,%6,%7}, {%8,%9}, {%0,%1,%2,%3};"
        : "+f"(d[0]), "+f"(d[1]), "+f"(d[2]), "+f"(d[3])
        : "r"(a[0]), "r"(a[1]), "r"(a[2]), "r"(a[3]), "r"(b[0]), "r"(b[1]));
}

// MODE 0: C = relu(A*B^T + bias[n]);  MODE 1: C = A*B^T + X[m][n]
template <int MODE>
__global__ __launch_bounds__(256, 1)
void k_gemm_mma(const uint4* __restrict__ A4, const uint4* __restrict__ B4,
                const float* __restrict__ X, float* __restrict__ C, int M) {
    extern __shared__ uint4 sbuf[];
    int tid = threadIdx.x;
    int lane = tid & 31, wid = tid >> 5;
    int warpM = wid >> 2;
    int warpN = wid & 3;
    int g = lane >> 2, t = lane & 3;
    int m0 = blockIdx.y * 128;
    int n0 = blockIdx.x * 128;

    // staging mapping: 256 threads -> 128 rows x 2 halves (2 uint4 each)
    int lr = tid >> 1;
    int h = tid & 1;
    const uint4* Ag = A4 + (size_t)(m0 + lr) * 128 + 2 * h;
    const uint4* Bg = B4 + (size_t)(n0 + lr) * 128 + 2 * h;

    float acc[4][4][4];
    #pragma unroll
    for (int i = 0; i < 4; i++)
        #pragma unroll
        for (int j = 0; j < 4; j++)
            #pragma unroll
            for (int k = 0; k < 4; k++) acc[i][j][k] = 0.f;

    // prologue: stages 0,1
    #pragma unroll
    for (int p = 0; p < 2; p++) {
        uint32_t da = smem_u32(&SB(p, 0, lr, 2 * h));
        uint32_t db = smem_u32(&SB(p, 1, lr, 2 * h));
        cp16(da, Ag + p * 4);      cp16(da + 16, Ag + p * 4 + 1);
        cp16(db, Bg + p * 4);      cp16(db + 16, Bg + p * 4 + 1);
        cp_commit();
    }

    int arow = warpM * 64 + g;
    int bn = warpN * 32 + g;

    for (int kc = 0; kc < NKC; kc++) {
        if (kc >= NKC - 2) cp_wait0(); else cp_wait1();
        __syncthreads();

        // prefetch chunk kc+2 into stage (kc+2)%3 (overwrites stage of kc-1)
        if (kc + 2 < NKC) {
            int ps = (kc + 2) % 3;
            uint32_t da = smem_u32(&SB(ps, 0, lr, 2 * h));
            uint32_t db = smem_u32(&SB(ps, 1, lr, 2 * h));
            cp16(da, Ag + (kc + 2) * 4);  cp16(da + 16, Ag + (kc + 2) * 4 + 1);
            cp16(db, Bg + (kc + 2) * 4);  cp16(db + 16, Bg + (kc + 2) * 4 + 1);
            cp_commit();
        }

        int s = kc % 3;
        uint32_t a1[4][4], a2[4][4], b1[4][2], b2[4][2];
        #pragma unroll
        for (int mt = 0; mt < 4; mt++) {
            uint4 va  = SB(s, 0, arow + mt * 16, t);
            uint4 va8 = SB(s, 0, arow + mt * 16 + 8, t);
            a1[mt][0] = va.x; a1[mt][1] = va8.x; a1[mt][2] = va.y; a1[mt][3] = va8.y;
            a2[mt][0] = va.z; a2[mt][1] = va8.z; a2[mt][2] = va.w; a2[mt][3] = va8.w;
        }
        #pragma unroll
        for (int nt = 0; nt < 4; nt++) {
            uint4 vb = SB(s, 1, bn + nt * 8, t);
            b1[nt][0] = vb.x; b1[nt][1] = vb.y;
            b2[nt][0] = vb.z; b2[nt][1] = vb.w;
        }
        #pragma unroll
        for (int mt = 0; mt < 4; mt++)
            #pragma unroll
            for (int nt = 0; nt < 4; nt++) {
                mma_bf16(acc[mt][nt], a1[mt], b1[nt]);
                mma_bf16(acc[mt][nt], a1[mt], b2[nt]);
                mma_bf16(acc[mt][nt], a2[mt], b1[nt]);
            }
    }

    #pragma unroll
    for (int mt = 0; mt < 4; mt++) {
        int row0 = m0 + warpM * 64 + mt * 16 + g;
        #pragma unroll
        for (int half = 0; half < 2; half++) {
            int row = row0 + half * 8;
            if (row >= M) continue;
            #pragma unroll
            for (int nt = 0; nt < 4; nt++) {
                int col = n0 + warpN * 32 + nt * 8 + t * 2;
                float v0 = acc[mt][nt][half * 2 + 0];
                float v1 = acc[mt][nt][half * 2 + 1];
                if (MODE == 0) {
                    float2 bb = *(const float2*)&X[col];
                    v0 = fmaxf(v0 + bb.x, 0.f);
                    v1 = fmaxf(v1 + bb.y, 0.f);
                } else {
                    float2 xx = *(const float2*)&X[(size_t)row * FDIM + col];
                    v0 += xx.x;
                    v1 += xx.y;
                }
                *(float2*)&C[(size_t)row * FDIM + col] = make_float2(v0, v1);
            }
        }
    }
}

// ---------------- layernorm ----------------
__global__ void k_ln(float* __restrict__ io, const float* __restrict__ gamma,
                     const float* __restrict__ beta) {
    int r = blockIdx.x;
    int t = threadIdx.x;
    float4* row = ((float4*)io) + (size_t)r * F4;
    float4 v = row[t];
    float s = v.x + v.y + v.z + v.w;
    float q = v.x * v.x + v.y * v.y + v.z * v.z + v.w * v.w;
    #pragma unroll
    for (int off = 16; off; off >>= 1) {
        s += __shfl_xor_sync(0xffffffffu, s, off);
        q += __shfl_xor_sync(0xffffffffu, q, off);
    }
    __shared__ float ss[4], sq[4];
    if ((t & 31) == 0) { ss[t >> 5] = s; sq[t >> 5] = q; }
    __syncthreads();
    s = ss[0] + ss[1] + ss[2] + ss[3];
    q = sq[0] + sq[1] + sq[2] + sq[3];
    float mu = s * (1.f / FDIM);
    float var = q * (1.f / FDIM) - mu * mu;
    float inv = rsqrtf(var + LNEPS);
    float4 g = ((const float4*)gamma)[t];
    float4 bb = ((const float4*)beta)[t];
    v.x = (v.x - mu) * inv * g.x + bb.x;
    v.y = (v.y - mu) * inv * g.y + bb.y;
    v.z = (v.z - mu) * inv * g.z + bb.z;
    v.w = (v.w - mu) * inv * g.w + bb.w;
    row[t] = v;
}

// ---------------- launch ----------------
extern "C" void kernel_launch(void* const* d_in, const int* in_sizes, int n_in,
                              void* d_out, int out_size) {
    const float* x     = (const float*)d_in[0];
    const int*   ei    = (const int*)d_in[1];
    const float* ts    = (const float*)d_in[2];
    const float* Wt    = (const float*)d_in[3];
    const float* bt    = (const float*)d_in[4];
    const float* Wr    = (const float*)d_in[5];
    const float* gamma = (const float*)d_in[6];
    const float* beta  = (const float*)d_in[7];
    const void*  gt    = d_in[8];

    int n = in_sizes[0] / FDIM;
    int e = in_sizes[1] / 2;

    float *h0, *h1;
    uint4 *ca, *cx, *cwt, *cwr;
    cudaGetSymbolAddress((void**)&h0, g_h0);
    cudaGetSymbolAddress((void**)&h1, g_h1);
    cudaGetSymbolAddress((void**)&ca, g_ca);
    cudaGetSymbolAddress((void**)&cx, g_cx);
    cudaGetSymbolAddress((void**)&cwt, g_cwt);
    cudaGetSymbolAddress((void**)&cwr, g_cwr);

    cudaFuncSetAttribute(k_gemm_mma<0>, cudaFuncAttributeMaxDynamicSharedMemorySize, SMEMB);
    cudaFuncSetAttribute(k_gemm_mma<1>, cudaFuncAttributeMaxDynamicSharedMemorySize, SMEMB);

    const int tb = 256;
    k_prep<<<(n + tb - 1) / tb, tb>>>(ts, e, n, gt);
    k_edge_deg<<<(e + tb - 1) / tb, tb>>>(ei, ts, e);
    k_node<<<(n + tb - 1) / tb, tb>>>(n, gt);
    k_scan<<<1, 1024>>>(n);
    k_scatter<<<(e + tb - 1) / tb, tb>>>(ei, ts, e);

    // weight + x conversions (independent of diffusion)
    k_cvt<<<(512 * 64 + tb - 1) / tb, tb>>>(Wt, cwt, 512 * 64);
    k_cvt<<<(512 * 64 + tb - 1) / tb, tb>>>(Wr, cwr, 512 * 64);
    k_cvt<<<(n * 64 + tb - 1) / tb, tb>>>(x, cx, n * 64);

    // 5 Euler diffusion steps; result in h1
    k_diff<<<n, 128>>>((const float4*)x,  (float4*)h1);
    k_diff<<<n, 128>>>((const float4*)h1, (float4*)h0);
    k_diff<<<n, 128>>>((const float4*)h0, (float4*)h1);
    k_diff<<<n, 128>>>((const float4*)h1, (float4*)h0);
    k_diff<<<n, 128>>>((const float4*)h0, (float4*)h1);

    // convert diffused h
    k_cvt<<<(n * 64 + tb - 1) / tb, tb>>>(h1, ca, n * 64);

    float* out = (float*)d_out;
    dim3 gg(FDIM / 128, (n + 127) / 128);   // (4, 157)
    k_gemm_mma<0><<<gg, 256, SMEMB>>>(ca, cwt, bt, h0, n);   // h0 = relu(h@Wt^T + b)
    k_gemm_mma<1><<<gg, 256, SMEMB>>>(cx, cwr, h0, out, n);  // out = x@Wr^T + h0
    k_ln<<<n, 128>>>(out, gamma, beta);
}